// round 2
// baseline (speedup 1.0000x reference)
#include <cuda_runtime.h>
#include <math.h>

#define BN 2
#define KC 12
#define HH 120
#define WW 160
#define HW (HH*WW)          // 19200
#define NB 100
#define DD 128
#define DD2 (DD*DD)
#define NVOX (DD*DD*DD)     // 2097152
#define NVOXB (BN*NVOX)     // 4194304
#define FEAT_ELEMS (BN*15*NB*HW)        // 57,600,000
#define FK_OFF FEAT_ELEMS
#define MASK_OFF (FEAT_ELEMS + NVOXB)   // 61,794,304

// ---------------- scratch (device globals; no allocations) ----------------
__device__ float          g_sm[BN*KC*HW];   // softmax features
__device__ int            g_di[BN*HW];      // depth_index
__device__ unsigned char  g_sind[BN*HW];    // sem>=10 indicator
__device__ float          g_sd[BN*HW];      // clamped depth, then stuff_depth
__device__ float          g_sx[BN*WW];      // stuff_x after find_none
__device__ float          g_sy[BN*HH];      // stuff_y after find_none
__device__ unsigned char  g_fk[NVOXB];      // feat_kept
__device__ unsigned char  g_t0[NVOXB];      // temp volume
__device__ unsigned char  g_t1[NVOXB];      // temp volume
__device__ int            g_bp[BN];         // batch_point counts

// ---------------- stage 1: per-pixel softmax/argmax/depth ----------------
__global__ void k_pix(const float* __restrict__ sem, const float* __restrict__ depth){
    int i = blockIdx.x*blockDim.x + threadIdx.x;
    if (i == 0){ g_bp[0] = 0; g_bp[1] = 0; }
    if (i >= BN*HW) return;
    int b = i / HW, p = i - b*HW;
    const float* s = sem + (size_t)b*KC*HW + p;
    float v[KC]; float mx = -1e30f; int am = 0;
    #pragma unroll
    for (int k = 0; k < KC; k++){ v[k] = s[(size_t)k*HW]; if (v[k] > mx){ mx = v[k]; am = k; } }
    float sum = 0.f;
    #pragma unroll
    for (int k = 0; k < KC; k++){ v[k] = expf(v[k]-mx); sum += v[k]; }
    float inv = 1.f/sum;
    float* o = g_sm + (size_t)b*KC*HW + p;
    #pragma unroll
    for (int k = 0; k < KC; k++) o[(size_t)k*HW] = v[k]*inv;
    g_sind[i] = (unsigned char)(am >= 10);
    float dc = fminf(depth[i], 6.f);
    g_di[i] = (int)(dc/6.f*100.f);
    g_sd[i] = dc;  // clamped depth; erosion pass zeroes non-stuff pixels
}

// ---------------- stage 2: 5x5 erosion -> stuff_depth (in-place on g_sd) ----------------
__global__ void k_erode(){
    int i = blockIdx.x*blockDim.x + threadIdx.x;
    if (i >= BN*HW) return;
    int b = i / HW, p = i - b*HW, h = p / WW, w = p - h*WW;
    bool all1 = true;
    #pragma unroll
    for (int dh = -2; dh <= 2; dh++){
        int h2 = h + dh; if (h2 < 0 || h2 >= HH) continue;
        #pragma unroll
        for (int dw = -2; dw <= 2; dw++){
            int w2 = w + dw; if (w2 < 0 || w2 >= WW) continue;
            if (!g_sind[b*HW + h2*WW + w2]) all1 = false;
        }
    }
    if (!all1) g_sd[i] = 0.f;
}

// ---------------- stage 3: border padding + axis maxes + find_none ----------------
__device__ void find_none_dev(const float* a, int n, float* out){
    float suf[WW];  // n <= 160
    float run = INFINITY;
    for (int ii = n-1; ii >= 0; ii--){
        suf[ii] = run;
        float av = (a[ii] != 0.f) ? a[ii] : INFINITY;
        run = fminf(run, av);
    }
    float m = INFINITY;
    for (int ii = 0; ii < n; ii++){
        float l = isinf(m)      ? 0.f : m;
        float r = isinf(suf[ii])? 0.f : suf[ii];
        float val = (a[ii] == 0.f) ? fmaxf(l, r) : a[ii];
        if (val != 0.f) m = fminf(m, val);
        out[ii] = val;
    }
}

__global__ void k_small(){
    __shared__ float ymax[HH], xmax[WW], colm[WW], rowm[HH];
    __shared__ float vy, vyr, vx, vxr;
    int b = blockIdx.x, tid = threadIdx.x;
    const float* sd = g_sd + b*HW;
    for (int h = tid; h < HH; h += blockDim.x){
        float m = 0.f; for (int w = 0; w < WW; w++) m = fmaxf(m, sd[h*WW+w]); ymax[h] = m;
    }
    for (int w = tid; w < WW; w += blockDim.x){
        float m = 0.f; for (int h = 0; h < HH; h++) m = fmaxf(m, sd[h*WW+w]); xmax[w] = m;
    }
    __syncthreads();
    if (tid == 0){
        float a = 0.f; for (int h = 0; h < HH; h++)      if (ymax[h] != 0.f){ a = ymax[h]; break; } vy  = a;
        a = 0.f;       for (int h = HH-1; h >= 0; h--)   if (ymax[h] != 0.f){ a = ymax[h]; break; } vyr = a;
        a = 0.f;       for (int w = 0; w < WW; w++)      if (xmax[w] != 0.f){ a = xmax[w]; break; } vx  = a;
        a = 0.f;       for (int w = WW-1; w >= 0; w--)   if (xmax[w] != 0.f){ a = xmax[w]; break; } vxr = a;
    }
    __syncthreads();
    // sd with padded borders. Column fills use ORIGINAL values and override row
    // fills at the corners (matches .at[].set ordering in the reference).
    auto sdval = [&](int h, int w) -> float {
        float v = sd[h*WW + w];
        if (w == 0)      return (v != 0.f) ? v : vx;
        if (w == WW-1)   return (v != 0.f) ? v : vxr;
        if (h == 0)      return (v != 0.f) ? v : vy;
        if (h == HH-1)   return (v != 0.f) ? v : vyr;
        return v;
    };
    for (int w = tid; w < WW; w += blockDim.x){
        float m = 0.f; for (int h = 0; h < HH; h++) m = fmaxf(m, sdval(h, w)); colm[w] = m;
    }
    for (int h = tid; h < HH; h += blockDim.x){
        float m = 0.f; for (int w = 0; w < WW; w++) m = fmaxf(m, sdval(h, w)); rowm[h] = m;
    }
    __syncthreads();
    if (tid == 0) find_none_dev(colm, WW, g_sx + b*WW);
    if (tid == 1) find_none_dev(rowm, HH, g_sy + b*HH);
}

// ---------------- stage 4: features (the big streaming write) ----------------
__global__ void k_feat(const float* __restrict__ occ, float* __restrict__ out){
    int i = blockIdx.x*blockDim.x + threadIdx.x;
    const int W4 = WW/4;
    if (i >= FEAT_ELEMS/4) return;
    int w4 = i % W4; int r = i / W4;
    int h  = r % HH; r /= HH;
    int d  = r % NB; r /= NB;
    int c  = r % 15; int b = r / 15;
    float4 o;
    if (c < KC){
        o = *(const float4*)(g_sm + (size_t)(b*KC + c)*HW + h*WW + w4*4);
    } else {
        int base = b*HW + h*WW + w4*4;
        float sy = g_sy[b*HH + h];
        float res[4];
        #pragma unroll
        for (int l = 0; l < 4; l++){
            int di = g_di[base + l];
            if (c == 13){
                int df = d - di;
                res[l] = (df > 0) ? 1.f : ((df < 0) ? -1.f : 0.f);
            } else if (c == 14){
                res[l] = fabsf((float)(d - di)/100.f*6.f);
            } else { // c == 12 : depth_weight
                int w = w4*4 + l;
                int dmb = (int)(fminf(g_sx[b*WW + w], sy)/6.f*100.f);
                bool kp = (d > di - 3) && (d < dmb + 5);
                float ov = occ[(size_t)(b*NB + d)*HW + h*WW + w];
                res[l] = kp ? (1.f/(1.f + expf(-ov))) : 0.f;
            }
        }
        o = make_float4(res[0], res[1], res[2], res[3]);
    }
    ((float4*)out)[i] = o;
}

// ---------------- stage 5: voxel gather -> feat_kept ----------------
// kept is a 4-byte-per-element boolean (int32 {0,1} or float32 {0.,1.}):
// nonzero bit pattern <=> true for both, so test the raw word against 0.
__global__ void k_voxel(const float4* __restrict__ mapping,
                        const unsigned int* __restrict__ kept,
                        float* __restrict__ out){
    int v = blockIdx.x*blockDim.x + threadIdx.x;
    if (v >= NVOXB) return;
    float4 m = mapping[v];
    bool fk = false;
    if (kept[v] != 0u){
        int b = (int)m.x, x = (int)m.y, y = (int)m.z;
        int didx = (int)(m.w*100.f/6.f);
        int di  = g_di[b*HW + y*WW + x];
        int dmb = (int)(fminf(g_sx[b*WW + x], g_sy[b*HH + y])/6.f*100.f);
        fk = (didx > di - 3) && (didx < dmb + 5);
    }
    g_fk[v] = (unsigned char)fk;
    out[FK_OFF + v] = fk ? 1.f : 0.f;
}

// ---------------- separable 5-wide binary dilation passes ----------------
__device__ __forceinline__ unsigned char dil5(const unsigned char* in, int v, int c, int stride){
    unsigned char acc = 0;
    #pragma unroll
    for (int dd = -2; dd <= 2; dd++){
        int cc = c + dd;
        if (cc >= 0 && cc < DD) acc |= in[v + dd*stride];
    }
    return acc;
}

__global__ void k_dilz_fk(){   // g_fk -> g_t0 along z
    int v = blockIdx.x*blockDim.x + threadIdx.x;
    if (v >= NVOXB) return;
    g_t0[v] = dil5(g_fk, v, (v/DD2) % DD, DD2);
}
__global__ void k_dily(){      // g_t0 -> g_t1 along y
    int v = blockIdx.x*blockDim.x + threadIdx.x;
    if (v >= NVOXB) return;
    g_t1[v] = dil5(g_t0, v, (v/DD) % DD, DD);
}
__global__ void k_dilz_t1(){   // g_t1 -> g_t0 along z
    int v = blockIdx.x*blockDim.x + threadIdx.x;
    if (v >= NVOXB) return;
    g_t0[v] = dil5(g_t1, v, (v/DD2) % DD, DD2);
}

// x-dilation of g_t1 fused with padding_kept computation + batch_point count
__global__ void k_pk(const unsigned int* __restrict__ kept){
    __shared__ int scount;
    int v = blockIdx.x*blockDim.x + threadIdx.x;   // NVOXB % 256 == 0: all blocks full
    if (threadIdx.x == 0) scount = 0;
    __syncthreads();
    unsigned char acc = dil5(g_t1, v, v % DD, 1);
    bool a = acc && (kept[v] != 0u);
    if (a) atomicAdd(&scount, 1);
    g_t0[v] = (a && !g_fk[v]) ? 1 : 0;
    __syncthreads();
    if (threadIdx.x == 0 && scount) atomicAdd(&g_bp[v / NVOX], scount);
}

__global__ void k_fix(){
    int b = threadIdx.x;
    if (b < BN && g_bp[b] == 0)
        g_t0[b*NVOX + 127*DD2 + 127*DD + 127] = 1;
}

// union = feat_kept | padding_even (2x2x2 block-any snapped to even coords)
__global__ void k_union(){
    int i = blockIdx.x*blockDim.x + threadIdx.x;
    if (i >= NVOXB/8) return;
    int bx = i % (DD/2); int r = i/(DD/2);
    int by = r % (DD/2); r /= (DD/2);
    int bz = r % (DD/2); int b = r/(DD/2);
    int base = b*NVOX + (2*bz)*DD2 + (2*by)*DD + 2*bx;
    const int off[8] = {0, 1, DD, DD+1, DD2, DD2+1, DD2+DD, DD2+DD+1};
    unsigned char any = 0;
    #pragma unroll
    for (int j = 0; j < 8; j++) any |= g_t0[base + off[j]];
    #pragma unroll
    for (int j = 0; j < 8; j++){
        unsigned char u = g_fk[base + off[j]];
        if (j == 0) u |= any;           // even corner (2bz,2by,2bx)
        g_t1[base + off[j]] = u;
    }
}

// final x-dilation of g_t1 writing mask floats
__global__ void k_maskx(float* __restrict__ out){
    int v = blockIdx.x*blockDim.x + threadIdx.x;
    if (v >= NVOXB) return;
    unsigned char acc = dil5(g_t1, v, v % DD, 1);
    out[MASK_OFF + v] = acc ? 1.f : 0.f;
}

// ---------------- launch ----------------
extern "C" void kernel_launch(void* const* d_in, const int* in_sizes, int n_in,
                              void* d_out, int out_size){
    const float* sem   = (const float*)d_in[0];         // [2,12,120,160]
    const float* depth = (const float*)d_in[1];         // [2,1,120,160]
    const float* occ   = (const float*)d_in[2];         // [2,100,120,160]
    const unsigned int* kept = (const unsigned int*)d_in[3]; // [2,128,128,128] bool as 4-byte
    const float4* mapping = (const float4*)d_in[4];     // [2,128,128,128,4]
    float* out = (float*)d_out;

    const int T = 256;
    k_pix  <<<(BN*HW + T-1)/T, T>>>(sem, depth);
    k_erode<<<(BN*HW + T-1)/T, T>>>();
    k_small<<<BN, 256>>>();
    k_feat <<<(FEAT_ELEMS/4 + T-1)/T, T>>>(occ, out);
    k_voxel<<<NVOXB/T, T>>>(mapping, kept, out);
    // dilate feat_kept (z, y, then x fused into k_pk)
    k_dilz_fk<<<NVOXB/T, T>>>();
    k_dily   <<<NVOXB/T, T>>>();
    k_pk     <<<NVOXB/T, T>>>(kept);
    k_fix    <<<1, BN>>>();
    k_union  <<<(NVOXB/8)/T, T>>>();
    // dilate union -> mask
    k_dilz_t1<<<NVOXB/T, T>>>();
    k_dily   <<<NVOXB/T, T>>>();
    k_maskx  <<<NVOXB/T, T>>>(out);
}

// round 4
// speedup vs baseline: 1.3695x; 1.3695x over previous
#include <cuda_runtime.h>
#include <math.h>

#define BN 2
#define KC 12
#define HH 120
#define WW 160
#define HW (HH*WW)          // 19200
#define NB 100
#define DD 128
#define DD2 (DD*DD)
#define NVOX (DD*DD*DD)     // 2097152
#define NVOXB (BN*NVOX)     // 4194304
#define NW 4                // 32-bit words per x-row
#define ROWW (NW*DD)        // word stride per z-slice = 512
#define NWORDS (NVOXB/32)   // 131072
#define WPB 65536           // words per batch
#define FEAT_ELEMS (BN*15*NB*HW)        // 57,600,000
#define FK_OFF FEAT_ELEMS
#define MASK_OFF (FEAT_ELEMS + NVOXB)

// ---------------- scratch (device globals; no allocations) ----------------
__device__ float          g_sm[BN*KC*HW];   // softmax features
__device__ int            g_di[BN*HW];      // depth_index
__device__ unsigned char  g_sind[BN*HW];    // sem>=10 indicator
__device__ float          g_sd[BN*HW];      // clamped depth -> stuff_depth
__device__ float          g_sx[BN*WW];
__device__ float          g_sy[BN*HH];
__device__ unsigned int   g_pf[NWORDS];     // packed feat_kept
__device__ unsigned int   g_pk[NWORDS];     // packed kept
__device__ unsigned int   g_pa[NWORDS];     // packed temp
__device__ unsigned int   g_pb[NWORDS];     // packed temp
__device__ int            g_bp[BN];

// ---------------- stage 1: per-pixel softmax/argmax/depth ----------------
__global__ void k_pix(const float* __restrict__ sem, const float* __restrict__ depth){
    int i = blockIdx.x*blockDim.x + threadIdx.x;
    if (i == 0){ g_bp[0] = 0; g_bp[1] = 0; }
    if (i >= BN*HW) return;
    int b = i / HW, p = i - b*HW;
    const float* s = sem + (size_t)b*KC*HW + p;
    float v[KC]; float mx = -1e30f; int am = 0;
    #pragma unroll
    for (int k = 0; k < KC; k++){ v[k] = s[(size_t)k*HW]; if (v[k] > mx){ mx = v[k]; am = k; } }
    float sum = 0.f;
    #pragma unroll
    for (int k = 0; k < KC; k++){ v[k] = expf(v[k]-mx); sum += v[k]; }
    float inv = 1.f/sum;
    float* o = g_sm + (size_t)b*KC*HW + p;
    #pragma unroll
    for (int k = 0; k < KC; k++) o[(size_t)k*HW] = v[k]*inv;
    g_sind[i] = (unsigned char)(am >= 10);
    float dc = fminf(depth[i], 6.f);
    g_di[i] = (int)(dc/6.f*100.f);
    g_sd[i] = dc;
}

// ---------------- stage 2: 5x5 erosion ----------------
__global__ void k_erode(){
    int i = blockIdx.x*blockDim.x + threadIdx.x;
    if (i >= BN*HW) return;
    int b = i / HW, p = i - b*HW, h = p / WW, w = p - h*WW;
    bool all1 = true;
    #pragma unroll
    for (int dh = -2; dh <= 2; dh++){
        int h2 = h + dh; if (h2 < 0 || h2 >= HH) continue;
        #pragma unroll
        for (int dw = -2; dw <= 2; dw++){
            int w2 = w + dw; if (w2 < 0 || w2 >= WW) continue;
            if (!g_sind[b*HW + h2*WW + w2]) all1 = false;
        }
    }
    if (!all1) g_sd[i] = 0.f;
}

// ---------------- stage 3: border padding + axis maxes + find_none ----------------
__device__ void find_none_dev(const float* a, int n, float* out){
    float suf[WW];
    float run = INFINITY;
    for (int ii = n-1; ii >= 0; ii--){
        suf[ii] = run;
        float av = (a[ii] != 0.f) ? a[ii] : INFINITY;
        run = fminf(run, av);
    }
    float m = INFINITY;
    for (int ii = 0; ii < n; ii++){
        float l = isinf(m)      ? 0.f : m;
        float r = isinf(suf[ii])? 0.f : suf[ii];
        float val = (a[ii] == 0.f) ? fmaxf(l, r) : a[ii];
        if (val != 0.f) m = fminf(m, val);
        out[ii] = val;
    }
}

__global__ void k_small(){
    __shared__ float ymax[HH], xmax[WW], colm[WW], rowm[HH];
    __shared__ float vy, vyr, vx, vxr;
    int b = blockIdx.x, tid = threadIdx.x;
    const float* sd = g_sd + b*HW;
    for (int h = tid; h < HH; h += blockDim.x){
        float m = 0.f; for (int w = 0; w < WW; w++) m = fmaxf(m, sd[h*WW+w]); ymax[h] = m;
    }
    for (int w = tid; w < WW; w += blockDim.x){
        float m = 0.f; for (int h = 0; h < HH; h++) m = fmaxf(m, sd[h*WW+w]); xmax[w] = m;
    }
    __syncthreads();
    if (tid == 0){
        float a = 0.f; for (int h = 0; h < HH; h++)      if (ymax[h] != 0.f){ a = ymax[h]; break; } vy  = a;
        a = 0.f;       for (int h = HH-1; h >= 0; h--)   if (ymax[h] != 0.f){ a = ymax[h]; break; } vyr = a;
        a = 0.f;       for (int w = 0; w < WW; w++)      if (xmax[w] != 0.f){ a = xmax[w]; break; } vx  = a;
        a = 0.f;       for (int w = WW-1; w >= 0; w--)   if (xmax[w] != 0.f){ a = xmax[w]; break; } vxr = a;
    }
    __syncthreads();
    auto sdval = [&](int h, int w) -> float {
        float v = sd[h*WW + w];
        if (w == 0)      return (v != 0.f) ? v : vx;
        if (w == WW-1)   return (v != 0.f) ? v : vxr;
        if (h == 0)      return (v != 0.f) ? v : vy;
        if (h == HH-1)   return (v != 0.f) ? v : vyr;
        return v;
    };
    for (int w = tid; w < WW; w += blockDim.x){
        float m = 0.f; for (int h = 0; h < HH; h++) m = fmaxf(m, sdval(h, w)); colm[w] = m;
    }
    for (int h = tid; h < HH; h += blockDim.x){
        float m = 0.f; for (int w = 0; w < WW; w++) m = fmaxf(m, sdval(h, w)); rowm[h] = m;
    }
    __syncthreads();
    // run the two serial scans on DIFFERENT warps so they execute concurrently
    if (tid == 0)  find_none_dev(colm, WW, g_sx + b*WW);
    if (tid == 32) find_none_dev(rowm, HH, g_sy + b*HH);
}

// ---------------- stage 4: features (store-bound streaming write) ----------------
// grid (30, 100, 30): x covers HW/4=4800 float4s with 160-thread blocks,
// y = depth bin, z = b*15 + channel (branch is block-uniform).
__global__ void k_feat(const float* __restrict__ occ, float* __restrict__ out){
    int p4 = blockIdx.x*160 + threadIdx.x;   // 0..4799
    int d  = blockIdx.y;
    int cz = blockIdx.z; int b = cz/15, c = cz - b*15;
    float4 o;
    if (c < KC){
        o = ((const float4*)g_sm)[(size_t)(b*KC + c)*(HW/4) + p4];
    } else if (c == 13){
        const int4 di4 = ((const int4*)g_di)[b*(HW/4) + p4];
        o.x = (d > di4.x) ? 1.f : ((d < di4.x) ? -1.f : 0.f);
        o.y = (d > di4.y) ? 1.f : ((d < di4.y) ? -1.f : 0.f);
        o.z = (d > di4.z) ? 1.f : ((d < di4.z) ? -1.f : 0.f);
        o.w = (d > di4.w) ? 1.f : ((d < di4.w) ? -1.f : 0.f);
    } else if (c == 14){
        const int4 di4 = ((const int4*)g_di)[b*(HW/4) + p4];
        o.x = fabsf((float)(d - di4.x)*0.06f);
        o.y = fabsf((float)(d - di4.y)*0.06f);
        o.z = fabsf((float)(d - di4.z)*0.06f);
        o.w = fabsf((float)(d - di4.w)*0.06f);
    } else { // c == 12 : depth_weight
        int h = p4/40, w0 = (p4 - h*40)*4;
        float sy = g_sy[b*HH + h];
        const int4 di4 = ((const int4*)g_di)[b*(HW/4) + p4];
        float4 ov = ((const float4*)occ)[(size_t)(b*NB + d)*(HW/4) + p4];
        int di[4] = {di4.x, di4.y, di4.z, di4.w};
        float ovv[4] = {ov.x, ov.y, ov.z, ov.w};
        float res[4];
        #pragma unroll
        for (int l = 0; l < 4; l++){
            int dmb = (int)(fminf(g_sx[b*WW + w0 + l], sy)/6.f*100.f);
            bool kp = (d > di[l] - 3) && (d < dmb + 5);
            res[l] = kp ? (1.f/(1.f + expf(-ovv[l]))) : 0.f;
        }
        o = make_float4(res[0], res[1], res[2], res[3]);
    }
    ((float4*)out)[((size_t)cz*NB + d)*(HW/4) + p4] = o;
}

// ---------------- stage 5: voxel gather -> feat_kept (predicated + ballot pack) ----------------
__global__ void k_voxel(const float4* __restrict__ mapping,
                        const unsigned int* __restrict__ kept,
                        float* __restrict__ out){
    int v = blockIdx.x*blockDim.x + threadIdx.x;
    bool kp = (kept[v] != 0u);
    bool fk = false;
    if (kp){
        float4 m = mapping[v];         // loaded only where kept
        int b = (int)m.x, x = (int)m.y, y = (int)m.z;
        int didx = (int)(m.w*100.f/6.f);
        int di  = g_di[b*HW + y*WW + x];
        int dmb = (int)(fminf(g_sx[b*WW + x], g_sy[b*HH + y])/6.f*100.f);
        fk = (didx > di - 3) && (didx < dmb + 5);
    }
    unsigned bf = __ballot_sync(0xffffffffu, fk);
    unsigned bk = __ballot_sync(0xffffffffu, kp);
    if ((threadIdx.x & 31) == 0){
        g_pf[v >> 5] = bf;
        g_pk[v >> 5] = bk;
    }
    out[FK_OFF + v] = fk ? 1.f : 0.f;
}

// ---------------- packed 5^3 dilation helpers (device pointers only) ----------------
__device__ __forceinline__ unsigned zydil(const unsigned int* in, int i){
    int t = i >> 2;
    int y = t & (DD-1);
    int z = (t >> 7) & (DD-1);
    unsigned acc = 0;
    #pragma unroll
    for (int dz = -2; dz <= 2; dz++){
        int zz = z + dz; if (zz < 0 || zz >= DD) continue;
        #pragma unroll
        for (int dy = -2; dy <= 2; dy++){
            int yy = y + dy; if (yy < 0 || yy >= DD) continue;
            acc |= in[i + (dz*DD + dy)*NW];
        }
    }
    return acc;
}

__device__ __forceinline__ unsigned xdil(const unsigned int* in, int i){
    int wx = i & (NW-1);
    unsigned c = in[i];
    unsigned p = wx ? in[i-1] : 0u;
    unsigned n = (wx < NW-1) ? in[i+1] : 0u;
    return c | (c<<1) | (c<<2) | (c>>1) | (c>>2)
             | (p>>31) | (p>>30) | (n<<31) | (n<<30);
}

// NOTE: all kernels reference the device globals DIRECTLY (never pass a
// __device__ symbol as a host-side kernel argument — that is UB and was the
// round-3 bug).
__global__ void k_dzy_f(){ int i = blockIdx.x*256 + threadIdx.x; g_pa[i] = zydil(g_pf, i); }
__global__ void k_dx_ab(){ int i = blockIdx.x*256 + threadIdx.x; g_pb[i] = xdil (g_pa, i); }
__global__ void k_dzy_b(){ int i = blockIdx.x*256 + threadIdx.x; g_pa[i] = zydil(g_pb, i); }

// padding_kept = dil3d(feat_kept) & kept; batch_point popcount; &= ~feat_kept
__global__ void k_pkw(){
    __shared__ int sc;
    int i = blockIdx.x*256 + threadIdx.x;
    if (threadIdx.x == 0) sc = 0;
    __syncthreads();
    unsigned a = g_pb[i] & g_pk[i];
    int cnt = __popc(a);
    #pragma unroll
    for (int off = 16; off > 0; off >>= 1) cnt += __shfl_down_sync(0xffffffffu, cnt, off);
    if ((threadIdx.x & 31) == 0 && cnt) atomicAdd(&sc, cnt);
    g_pa[i] = a & ~g_pf[i];
    __syncthreads();
    if (threadIdx.x == 0 && sc) atomicAdd(&g_bp[i >> 16], sc);
}

__global__ void k_fix(){
    int b = threadIdx.x;
    if (b < BN && g_bp[b] == 0)
        g_pa[b*WPB + 127*ROWW + 127*NW + 3] |= 0x80000000u;
}

// union = feat_kept | padding_even (2x2x2 block-any snapped to even coords)
__global__ void k_unionw(){
    int i = blockIdx.x*256 + threadIdx.x;
    int t = i >> 2;
    int y = t & (DD-1);
    int z = (t >> 7) & (DD-1);
    unsigned pe = 0;
    if (!(y & 1) && !(z & 1)){
        unsigned q = g_pa[i] | g_pa[i+NW] | g_pa[i+ROWW] | g_pa[i+ROWW+NW];
        pe = (q | (q >> 1)) & 0x55555555u;
    }
    g_pb[i] = g_pf[i] | pe;
}

// final x-dilation + unpack to float mask output
__global__ void k_maskx(float* __restrict__ out){
    int i = blockIdx.x*256 + threadIdx.x;
    unsigned r = xdil(g_pa, i);
    float4* o = (float4*)(out + MASK_OFF + (size_t)i*32);
    #pragma unroll
    for (int j = 0; j < 8; j++){
        o[j] = make_float4((r>>(4*j))&1 ? 1.f:0.f, (r>>(4*j+1))&1 ? 1.f:0.f,
                           (r>>(4*j+2))&1 ? 1.f:0.f, (r>>(4*j+3))&1 ? 1.f:0.f);
    }
}

// ---------------- launch ----------------
extern "C" void kernel_launch(void* const* d_in, const int* in_sizes, int n_in,
                              void* d_out, int out_size){
    const float* sem   = (const float*)d_in[0];
    const float* depth = (const float*)d_in[1];
    const float* occ   = (const float*)d_in[2];
    const unsigned int* kept = (const unsigned int*)d_in[3];
    const float4* mapping = (const float4*)d_in[4];
    float* out = (float*)d_out;

    const int T = 256;
    const int WG = NWORDS/256;  // 512
    k_pix  <<<(BN*HW + T-1)/T, T>>>(sem, depth);
    k_erode<<<(BN*HW + T-1)/T, T>>>();
    k_small<<<BN, 256>>>();
    k_feat <<<dim3(30, NB, BN*15), 160>>>(occ, out);
    k_voxel<<<NVOXB/T, T>>>(mapping, kept, out);
    // dil3d(feat_kept): (z,y) pass then x pass
    k_dzy_f<<<WG, T>>>();
    k_dx_ab<<<WG, T>>>();
    k_pkw  <<<WG, T>>>();
    k_fix  <<<1, BN>>>();
    k_unionw<<<WG, T>>>();
    // dil3d(union) -> mask
    k_dzy_b<<<WG, T>>>();
    k_maskx<<<WG, T>>>(out);
}